// round 1
// baseline (speedup 1.0000x reference)
#include <cuda_runtime.h>

#define S_  16
#define A_  16
#define DA_ 128
#define DS_ 128
#define H_  64
#define TB  128
#define NTHREADS 256

#define AS_LD 132   // padded stride for action tile (128 + 4)
#define H_LD  68    // padded stride for h1/h2 tiles (64 + 4)

// smem floats: As + W1 + h1 + W2 + h2 + W3 + b1 + b2 + b3
#define SMEM_FLOATS (TB*AS_LD + DA_*H_ + TB*H_LD + H_*H_ + TB*H_LD + H_*DS_ + H_ + H_ + DS_)
#define SMEM_BYTES  (SMEM_FLOATS * 4)

__device__ int g_mask[S_ * A_];

// causal_relation arrives as bool; serialized dtype is ambiguous (int32 / float32 /
// raw bytes). Sniff it from the first 256 bytes (safe for all interpretations) and
// normalize to g_mask. Deterministic.
__global__ void prep_mask_kernel(const unsigned* __restrict__ rel) {
    if (threadIdx.x != 0) return;
    bool allint = true, allfloat = true;
    for (int i = 0; i < 64; i++) {
        unsigned u = rel[i];
        if (u > 1u) allint = false;
        if (!(u == 0u || u == 0x3F800000u)) allfloat = false;
    }
    if (allint) {
        const int* p = (const int*)rel;
        for (int i = 0; i < S_ * A_; i++) g_mask[i] = (p[i] != 0);
    } else if (allfloat) {
        const float* p = (const float*)rel;
        for (int i = 0; i < S_ * A_; i++) g_mask[i] = (p[i] != 0.0f);
    } else {
        const unsigned char* p = (const unsigned char*)rel;
        for (int i = 0; i < S_ * A_; i++) g_mask[i] = (p[i] != 0);
    }
}

__global__ __launch_bounds__(NTHREADS, 1)
void expert_kernel(const float* __restrict__ state,
                   const float* __restrict__ act,
                   const float* __restrict__ W1, const float* __restrict__ b1,
                   const float* __restrict__ W2, const float* __restrict__ b2,
                   const float* __restrict__ W3, const float* __restrict__ b3,
                   float* __restrict__ out)
{
    extern __shared__ float sm[];
    float* As  = sm;                   // TB x AS_LD
    float* W1s = As  + TB * AS_LD;     // DA_ x H_   (row-major [d][h])
    float* h1s = W1s + DA_ * H_;       // TB x H_LD
    float* W2s = h1s + TB * H_LD;      // H_ x H_
    float* h2s = W2s + H_ * H_;        // TB x H_LD
    float* W3s = h2s + TB * H_LD;      // H_ x DS_
    float* b1s = W3s + H_ * DS_;       // H_
    float* b2s = b1s + H_;             // H_
    float* b3s = b2s + H_;             // DS_

    const int s   = blockIdx.y;
    const int b0  = blockIdx.x * TB;
    const int tid = threadIdx.x;
    const int tx  = tid & 15;          // 16 col-groups
    const int ty  = tid >> 4;          // 16 row-groups

    // persistent output accumulator: rows (ty + 16*r), cols (tx*8 + c)
    float acc_out[8][8];
    #pragma unroll
    for (int r = 0; r < 8; r++)
        #pragma unroll
        for (int c = 0; c < 8; c++) acc_out[r][c] = 0.0f;

    for (int a = 0; a < A_; a++) {
        if (!g_mask[s * A_ + a]) continue;
        __syncthreads();   // previous iteration done reading h2s/W3s

        // ---- stage inputs: action tile + W1/W2/W3 + biases ----
        {
            const float* src = act + (size_t)b0 * (A_ * DA_) + a * DA_;
            for (int i = tid; i < TB * (DA_ / 4); i += NTHREADS) {
                int r = i >> 5, c4 = (i & 31) * 4;
                *(float4*)(As + r * AS_LD + c4) =
                    *(const float4*)(src + (size_t)r * (A_ * DA_) + c4);
            }
        }
        {
            const float* p = W1 + (size_t)(s * A_ + a) * DA_ * H_;
            for (int i = tid; i < DA_ * H_ / 4; i += NTHREADS)
                *(float4*)(W1s + i * 4) = *(const float4*)(p + i * 4);
        }
        {
            const float* p = W2 + (size_t)(s * A_ + a) * H_ * H_;
            for (int i = tid; i < H_ * H_ / 4; i += NTHREADS)
                *(float4*)(W2s + i * 4) = *(const float4*)(p + i * 4);
        }
        {
            const float* p = W3 + (size_t)(s * A_ + a) * H_ * DS_;
            for (int i = tid; i < H_ * DS_ / 4; i += NTHREADS)
                *(float4*)(W3s + i * 4) = *(const float4*)(p + i * 4);
        }
        if (tid < H_)            b1s[tid]         = b1[(s * A_ + a) * H_ + tid];
        else if (tid < 2 * H_)   b2s[tid - H_]    = b2[(s * A_ + a) * H_ + tid - H_];
        else                     b3s[tid - 2*H_]  = b3[(s * A_ + a) * DS_ + tid - 2*H_];
        __syncthreads();

        // ---- GEMM1: h1[TB x 64] = relu(As[TB x 128] @ W1s[128 x 64] + b1) ----
        {
            float acc[8][4];
            #pragma unroll
            for (int r = 0; r < 8; r++) { acc[r][0]=0; acc[r][1]=0; acc[r][2]=0; acc[r][3]=0; }
            #pragma unroll 2
            for (int k4 = 0; k4 < DA_; k4 += 4) {
                float4 av[8];
                #pragma unroll
                for (int r = 0; r < 8; r++)
                    av[r] = *(float4*)(As + (ty + 16 * r) * AS_LD + k4);
                #pragma unroll
                for (int kk = 0; kk < 4; kk++) {
                    float4 w = *(float4*)(W1s + (k4 + kk) * H_ + tx * 4);
                    #pragma unroll
                    for (int r = 0; r < 8; r++) {
                        float aval = (kk==0) ? av[r].x : (kk==1) ? av[r].y : (kk==2) ? av[r].z : av[r].w;
                        acc[r][0] += aval * w.x; acc[r][1] += aval * w.y;
                        acc[r][2] += aval * w.z; acc[r][3] += aval * w.w;
                    }
                }
            }
            float4 bv = *(float4*)(b1s + tx * 4);
            #pragma unroll
            for (int r = 0; r < 8; r++) {
                float4 o;
                o.x = fmaxf(acc[r][0] + bv.x, 0.0f);
                o.y = fmaxf(acc[r][1] + bv.y, 0.0f);
                o.z = fmaxf(acc[r][2] + bv.z, 0.0f);
                o.w = fmaxf(acc[r][3] + bv.w, 0.0f);
                *(float4*)(h1s + (ty + 16 * r) * H_LD + tx * 4) = o;
            }
        }
        __syncthreads();

        // ---- GEMM2: h2[TB x 64] = relu(h1 @ W2s[64 x 64] + b2) ----
        {
            float acc[8][4];
            #pragma unroll
            for (int r = 0; r < 8; r++) { acc[r][0]=0; acc[r][1]=0; acc[r][2]=0; acc[r][3]=0; }
            #pragma unroll 2
            for (int k4 = 0; k4 < H_; k4 += 4) {
                float4 hv[8];
                #pragma unroll
                for (int r = 0; r < 8; r++)
                    hv[r] = *(float4*)(h1s + (ty + 16 * r) * H_LD + k4);
                #pragma unroll
                for (int kk = 0; kk < 4; kk++) {
                    float4 w = *(float4*)(W2s + (k4 + kk) * H_ + tx * 4);
                    #pragma unroll
                    for (int r = 0; r < 8; r++) {
                        float hval = (kk==0) ? hv[r].x : (kk==1) ? hv[r].y : (kk==2) ? hv[r].z : hv[r].w;
                        acc[r][0] += hval * w.x; acc[r][1] += hval * w.y;
                        acc[r][2] += hval * w.z; acc[r][3] += hval * w.w;
                    }
                }
            }
            float4 bv = *(float4*)(b2s + tx * 4);
            #pragma unroll
            for (int r = 0; r < 8; r++) {
                float4 o;
                o.x = fmaxf(acc[r][0] + bv.x, 0.0f);
                o.y = fmaxf(acc[r][1] + bv.y, 0.0f);
                o.z = fmaxf(acc[r][2] + bv.z, 0.0f);
                o.w = fmaxf(acc[r][3] + bv.w, 0.0f);
                *(float4*)(h2s + (ty + 16 * r) * H_LD + tx * 4) = o;
            }
        }
        __syncthreads();

        // ---- GEMM3: acc_out += relu(h2 @ W3s[64 x 128] + b3) ----
        {
            float acc[8][8];
            #pragma unroll
            for (int r = 0; r < 8; r++)
                #pragma unroll
                for (int c = 0; c < 8; c++) acc[r][c] = 0.0f;
            #pragma unroll 2
            for (int k4 = 0; k4 < H_; k4 += 4) {
                float4 hv[8];
                #pragma unroll
                for (int r = 0; r < 8; r++)
                    hv[r] = *(float4*)(h2s + (ty + 16 * r) * H_LD + k4);
                #pragma unroll
                for (int kk = 0; kk < 4; kk++) {
                    float4 w0 = *(float4*)(W3s + (k4 + kk) * DS_ + tx * 8);
                    float4 w1 = *(float4*)(W3s + (k4 + kk) * DS_ + tx * 8 + 4);
                    #pragma unroll
                    for (int r = 0; r < 8; r++) {
                        float hval = (kk==0) ? hv[r].x : (kk==1) ? hv[r].y : (kk==2) ? hv[r].z : hv[r].w;
                        acc[r][0] += hval * w0.x; acc[r][1] += hval * w0.y;
                        acc[r][2] += hval * w0.z; acc[r][3] += hval * w0.w;
                        acc[r][4] += hval * w1.x; acc[r][5] += hval * w1.y;
                        acc[r][6] += hval * w1.z; acc[r][7] += hval * w1.w;
                    }
                }
            }
            float4 bv0 = *(float4*)(b3s + tx * 8);
            float4 bv1 = *(float4*)(b3s + tx * 8 + 4);
            #pragma unroll
            for (int r = 0; r < 8; r++) {
                acc_out[r][0] += fmaxf(acc[r][0] + bv0.x, 0.0f);
                acc_out[r][1] += fmaxf(acc[r][1] + bv0.y, 0.0f);
                acc_out[r][2] += fmaxf(acc[r][2] + bv0.z, 0.0f);
                acc_out[r][3] += fmaxf(acc[r][3] + bv0.w, 0.0f);
                acc_out[r][4] += fmaxf(acc[r][4] + bv1.x, 0.0f);
                acc_out[r][5] += fmaxf(acc[r][5] + bv1.y, 0.0f);
                acc_out[r][6] += fmaxf(acc[r][6] + bv1.z, 0.0f);
                acc_out[r][7] += fmaxf(acc[r][7] + bv1.w, 0.0f);
            }
        }
    }

    // ---- epilogue: out = state + diff ----
    #pragma unroll
    for (int r = 0; r < 8; r++) {
        int brow = b0 + ty + 16 * r;
        size_t base = ((size_t)brow * S_ + s) * DS_ + tx * 8;
        float4 s0 = *(const float4*)(state + base);
        float4 s1 = *(const float4*)(state + base + 4);
        float4 o0, o1;
        o0.x = s0.x + acc_out[r][0]; o0.y = s0.y + acc_out[r][1];
        o0.z = s0.z + acc_out[r][2]; o0.w = s0.w + acc_out[r][3];
        o1.x = s1.x + acc_out[r][4]; o1.y = s1.y + acc_out[r][5];
        o1.z = s1.z + acc_out[r][6]; o1.w = s1.w + acc_out[r][7];
        *(float4*)(out + base)     = o0;
        *(float4*)(out + base + 4) = o1;
    }
}

extern "C" void kernel_launch(void* const* d_in, const int* in_sizes, int n_in,
                              void* d_out, int out_size)
{
    const float* state = (const float*)d_in[0];
    const float* act   = (const float*)d_in[1];
    const void*  rel   = d_in[2];
    const float* W1 = (const float*)d_in[3];
    const float* b1 = (const float*)d_in[4];
    const float* W2 = (const float*)d_in[5];
    const float* b2 = (const float*)d_in[6];
    const float* W3 = (const float*)d_in[7];
    const float* b3 = (const float*)d_in[8];
    float* out = (float*)d_out;

    const int B = in_sizes[0] / (S_ * DS_);

    cudaFuncSetAttribute(expert_kernel,
                         cudaFuncAttributeMaxDynamicSharedMemorySize, SMEM_BYTES);

    prep_mask_kernel<<<1, 32>>>((const unsigned*)rel);

    dim3 grid(B / TB, S_);
    expert_kernel<<<grid, NTHREADS, SMEM_BYTES>>>(
        state, act, W1, b1, W2, b2, W3, b3, out);
}

// round 2
// speedup vs baseline: 1.6690x; 1.6690x over previous
#include <cuda_runtime.h>

#define S_  16
#define A_  16
#define DA_ 128
#define DS_ 128
#define H_  64
#define TB  128
#define NTHREADS 256

#define AS_LD 132   // As: 128x132 (tf32 bits), bank = (4r+q)%32 conflict-free
#define W1_LD 132   // W1s: [n=64][k=132]
#define H_LD  68    // h1s/h2s: 128x68
#define W2_LD 68    // W2s: [n=64][k=68]
#define W3_LD 68    // W3s: [n=128][k=68]

// smem (floats/uints, all 4B):
#define OFF_AS   0
#define OFF_W1   (OFF_AS  + TB  * AS_LD)     // 16896
#define OFF_H1   (OFF_W1  + H_  * W1_LD)     // +8448
#define OFF_W2   (OFF_H1  + TB  * H_LD)      // +8704
#define OFF_H2   (OFF_W2  + H_  * W2_LD)     // +4352
#define OFF_W3   (OFF_H2  + TB  * H_LD)      // +8704
#define OFF_B1   (OFF_W3  + DS_ * W3_LD)     // +8704
#define OFF_B2   (OFF_B1  + H_)
#define OFF_B3   (OFF_B2  + H_)
#define SMEM_WORDS (OFF_B3 + DS_)
#define SMEM_BYTES (SMEM_WORDS * 4)

__device__ int g_mask[S_ * A_];

__global__ void prep_mask_kernel(const unsigned* __restrict__ rel) {
    if (threadIdx.x != 0) return;
    bool allint = true, allfloat = true;
    for (int i = 0; i < 64; i++) {
        unsigned u = rel[i];
        if (u > 1u) allint = false;
        if (!(u == 0u || u == 0x3F800000u)) allfloat = false;
    }
    if (allint) {
        const int* p = (const int*)rel;
        for (int i = 0; i < S_ * A_; i++) g_mask[i] = (p[i] != 0);
    } else if (allfloat) {
        const float* p = (const float*)rel;
        for (int i = 0; i < S_ * A_; i++) g_mask[i] = (p[i] != 0.0f);
    } else {
        const unsigned char* p = (const unsigned char*)rel;
        for (int i = 0; i < S_ * A_; i++) g_mask[i] = (p[i] != 0);
    }
}

__device__ __forceinline__ unsigned f2tf(float f) {
    unsigned u;
    asm("cvt.rna.tf32.f32 %0, %1;" : "=r"(u) : "f"(f));
    return u;
}

__device__ __forceinline__ void mma_tf32(float& d0, float& d1, float& d2, float& d3,
                                         unsigned a0, unsigned a1, unsigned a2, unsigned a3,
                                         unsigned b0, unsigned b1) {
    asm volatile(
        "mma.sync.aligned.m16n8k8.row.col.f32.tf32.tf32.f32 "
        "{%0,%1,%2,%3}, {%4,%5,%6,%7}, {%8,%9}, {%0,%1,%2,%3};"
        : "+f"(d0), "+f"(d1), "+f"(d2), "+f"(d3)
        : "r"(a0), "r"(a1), "r"(a2), "r"(a3), "r"(b0), "r"(b1));
}

__global__ __launch_bounds__(NTHREADS, 1)
void expert_kernel(const float* __restrict__ state,
                   const float* __restrict__ act,
                   const float* __restrict__ W1, const float* __restrict__ b1,
                   const float* __restrict__ W2, const float* __restrict__ b2,
                   const float* __restrict__ W3, const float* __restrict__ b3,
                   float* __restrict__ out)
{
    extern __shared__ unsigned sm[];
    unsigned* As  = sm + OFF_AS;
    unsigned* W1s = sm + OFF_W1;
    unsigned* h1s = sm + OFF_H1;
    unsigned* W2s = sm + OFF_W2;
    unsigned* h2s = sm + OFF_H2;
    unsigned* W3s = sm + OFF_W3;
    float* b1s = (float*)(sm + OFF_B1);
    float* b2s = (float*)(sm + OFF_B2);
    float* b3s = (float*)(sm + OFF_B3);

    const int s    = blockIdx.y;
    const int b0   = blockIdx.x * TB;
    const int tid  = threadIdx.x;
    const int lane = tid & 31;
    const int warp = tid >> 5;
    const int wm   = warp & 3;   // 4 warp-rows of m32
    const int wn   = warp >> 2;  // 2 warp-cols
    const int r    = lane >> 2;  // 0..7
    const int q    = lane & 3;   // 0..3

    const int mrow0 = wm * 32 + r;        // mt adds 16
    const int hcol0 = wn * 32 + 2 * q;    // GEMM1/2 store col base (nt adds 8)

    // persistent masked-sum accumulator for GEMM3: [mt][nt][4]
    float acc[2][8][4];
    #pragma unroll
    for (int mt = 0; mt < 2; mt++)
        #pragma unroll
        for (int nt = 0; nt < 8; nt++)
            #pragma unroll
            for (int c = 0; c < 4; c++) acc[mt][nt][c] = 0.0f;

    for (int a = 0; a < A_; a++) {
        if (!g_mask[s * A_ + a]) continue;
        __syncthreads();   // prior iteration done reading h2s/W3s

        // ---------------- staging (tf32 convert) ----------------
        {   // action tile [128][128] -> As row-major
            const float* src = act + ((size_t)b0 * A_ + a) * DA_;
            for (int i = tid; i < TB * (DA_ / 4); i += NTHREADS) {
                int rr = i >> 5, c4 = (i & 31) * 4;
                float4 v = *(const float4*)(src + ((size_t)rr * A_) * DA_ + c4);
                uint4 u = { f2tf(v.x), f2tf(v.y), f2tf(v.z), f2tf(v.w) };
                *(uint4*)(As + rr * AS_LD + c4) = u;
            }
        }
        const size_t eoff = (size_t)(s * A_ + a);
        {   // W1 [k=128][n=64] -> W1s [n][k]
            const float* p = W1 + eoff * DA_ * H_;
            for (int i = tid; i < DA_ * H_ / 4; i += NTHREADS) {
                int lin = i * 4, k = lin >> 6, n0 = lin & 63;
                float4 v = *(const float4*)(p + lin);
                W1s[(n0 + 0) * W1_LD + k] = f2tf(v.x);
                W1s[(n0 + 1) * W1_LD + k] = f2tf(v.y);
                W1s[(n0 + 2) * W1_LD + k] = f2tf(v.z);
                W1s[(n0 + 3) * W1_LD + k] = f2tf(v.w);
            }
        }
        {   // W2 [k=64][n=64] -> W2s [n][k]
            const float* p = W2 + eoff * H_ * H_;
            for (int i = tid; i < H_ * H_ / 4; i += NTHREADS) {
                int lin = i * 4, k = lin >> 6, n0 = lin & 63;
                float4 v = *(const float4*)(p + lin);
                W2s[(n0 + 0) * W2_LD + k] = f2tf(v.x);
                W2s[(n0 + 1) * W2_LD + k] = f2tf(v.y);
                W2s[(n0 + 2) * W2_LD + k] = f2tf(v.z);
                W2s[(n0 + 3) * W2_LD + k] = f2tf(v.w);
            }
        }
        {   // W3 [k=64][n=128] -> W3s [n][k]
            const float* p = W3 + eoff * H_ * DS_;
            for (int i = tid; i < H_ * DS_ / 4; i += NTHREADS) {
                int lin = i * 4, k = lin >> 7, n0 = lin & 127;
                float4 v = *(const float4*)(p + lin);
                W3s[(n0 + 0) * W3_LD + k] = f2tf(v.x);
                W3s[(n0 + 1) * W3_LD + k] = f2tf(v.y);
                W3s[(n0 + 2) * W3_LD + k] = f2tf(v.z);
                W3s[(n0 + 3) * W3_LD + k] = f2tf(v.w);
            }
        }
        if (tid < H_)          b1s[tid]          = b1[eoff * H_ + tid];
        else if (tid < 2*H_)   b2s[tid - H_]     = b2[eoff * H_ + tid - H_];
        else                   b3s[tid - 2*H_]   = b3[eoff * DS_ + tid - 2*H_];
        __syncthreads();

        // ---------------- GEMM1: h1 = relu(A @ W1 + b1), M128 N64 K128 ----------------
        {
            float d[2][4][4];
            #pragma unroll
            for (int mt = 0; mt < 2; mt++)
                #pragma unroll
                for (int nt = 0; nt < 4; nt++)
                    { d[mt][nt][0]=0; d[mt][nt][1]=0; d[mt][nt][2]=0; d[mt][nt][3]=0; }
            #pragma unroll 4
            for (int k0 = 0; k0 < DA_; k0 += 8) {
                unsigned af[2][4], bf[4][2];
                #pragma unroll
                for (int mt = 0; mt < 2; mt++) {
                    const unsigned* base = As + (mrow0 + mt * 16) * AS_LD + k0 + q;
                    af[mt][0] = base[0];
                    af[mt][1] = base[8 * AS_LD];
                    af[mt][2] = base[4];
                    af[mt][3] = base[8 * AS_LD + 4];
                }
                #pragma unroll
                for (int nt = 0; nt < 4; nt++) {
                    const unsigned* base = W1s + (wn * 32 + nt * 8 + r) * W1_LD + k0 + q;
                    bf[nt][0] = base[0];
                    bf[nt][1] = base[4];
                }
                #pragma unroll
                for (int mt = 0; mt < 2; mt++)
                    #pragma unroll
                    for (int nt = 0; nt < 4; nt++)
                        mma_tf32(d[mt][nt][0], d[mt][nt][1], d[mt][nt][2], d[mt][nt][3],
                                 af[mt][0], af[mt][1], af[mt][2], af[mt][3],
                                 bf[nt][0], bf[nt][1]);
            }
            #pragma unroll
            for (int mt = 0; mt < 2; mt++)
                #pragma unroll
                for (int nt = 0; nt < 4; nt++) {
                    int col = hcol0 + nt * 8;
                    float bb0 = b1s[col], bb1 = b1s[col + 1];
                    int row = mrow0 + mt * 16;
                    uint2 u0 = { f2tf(fmaxf(d[mt][nt][0] + bb0, 0.0f)),
                                 f2tf(fmaxf(d[mt][nt][1] + bb1, 0.0f)) };
                    uint2 u1 = { f2tf(fmaxf(d[mt][nt][2] + bb0, 0.0f)),
                                 f2tf(fmaxf(d[mt][nt][3] + bb1, 0.0f)) };
                    *(uint2*)(h1s + row * H_LD + col)        = u0;
                    *(uint2*)(h1s + (row + 8) * H_LD + col)  = u1;
                }
        }
        __syncthreads();

        // ---------------- GEMM2: h2 = relu(h1 @ W2 + b2), M128 N64 K64 ----------------
        {
            float d[2][4][4];
            #pragma unroll
            for (int mt = 0; mt < 2; mt++)
                #pragma unroll
                for (int nt = 0; nt < 4; nt++)
                    { d[mt][nt][0]=0; d[mt][nt][1]=0; d[mt][nt][2]=0; d[mt][nt][3]=0; }
            #pragma unroll 4
            for (int k0 = 0; k0 < H_; k0 += 8) {
                unsigned af[2][4], bf[4][2];
                #pragma unroll
                for (int mt = 0; mt < 2; mt++) {
                    const unsigned* base = h1s + (mrow0 + mt * 16) * H_LD + k0 + q;
                    af[mt][0] = base[0];
                    af[mt][1] = base[8 * H_LD];
                    af[mt][2] = base[4];
                    af[mt][3] = base[8 * H_LD + 4];
                }
                #pragma unroll
                for (int nt = 0; nt < 4; nt++) {
                    const unsigned* base = W2s + (wn * 32 + nt * 8 + r) * W2_LD + k0 + q;
                    bf[nt][0] = base[0];
                    bf[nt][1] = base[4];
                }
                #pragma unroll
                for (int mt = 0; mt < 2; mt++)
                    #pragma unroll
                    for (int nt = 0; nt < 4; nt++)
                        mma_tf32(d[mt][nt][0], d[mt][nt][1], d[mt][nt][2], d[mt][nt][3],
                                 af[mt][0], af[mt][1], af[mt][2], af[mt][3],
                                 bf[nt][0], bf[nt][1]);
            }
            #pragma unroll
            for (int mt = 0; mt < 2; mt++)
                #pragma unroll
                for (int nt = 0; nt < 4; nt++) {
                    int col = hcol0 + nt * 8;
                    float bb0 = b2s[col], bb1 = b2s[col + 1];
                    int row = mrow0 + mt * 16;
                    uint2 u0 = { f2tf(fmaxf(d[mt][nt][0] + bb0, 0.0f)),
                                 f2tf(fmaxf(d[mt][nt][1] + bb1, 0.0f)) };
                    uint2 u1 = { f2tf(fmaxf(d[mt][nt][2] + bb0, 0.0f)),
                                 f2tf(fmaxf(d[mt][nt][3] + bb1, 0.0f)) };
                    *(uint2*)(h2s + row * H_LD + col)        = u0;
                    *(uint2*)(h2s + (row + 8) * H_LD + col)  = u1;
                }
        }
        __syncthreads();

        // ---------------- GEMM3: acc += relu(h2 @ W3 + b3), M128 N128 K64 ----------------
        {
            float d[2][8][4];
            #pragma unroll
            for (int mt = 0; mt < 2; mt++)
                #pragma unroll
                for (int nt = 0; nt < 8; nt++)
                    { d[mt][nt][0]=0; d[mt][nt][1]=0; d[mt][nt][2]=0; d[mt][nt][3]=0; }
            #pragma unroll 2
            for (int k0 = 0; k0 < H_; k0 += 8) {
                unsigned af[2][4], bf[8][2];
                #pragma unroll
                for (int mt = 0; mt < 2; mt++) {
                    const unsigned* base = h2s + (mrow0 + mt * 16) * H_LD + k0 + q;
                    af[mt][0] = base[0];
                    af[mt][1] = base[8 * H_LD];
                    af[mt][2] = base[4];
                    af[mt][3] = base[8 * H_LD + 4];
                }
                #pragma unroll
                for (int nt = 0; nt < 8; nt++) {
                    const unsigned* base = W3s + (wn * 64 + nt * 8 + r) * W3_LD + k0 + q;
                    bf[nt][0] = base[0];
                    bf[nt][1] = base[4];
                }
                #pragma unroll
                for (int mt = 0; mt < 2; mt++)
                    #pragma unroll
                    for (int nt = 0; nt < 8; nt++)
                        mma_tf32(d[mt][nt][0], d[mt][nt][1], d[mt][nt][2], d[mt][nt][3],
                                 af[mt][0], af[mt][1], af[mt][2], af[mt][3],
                                 bf[nt][0], bf[nt][1]);
            }
            #pragma unroll
            for (int mt = 0; mt < 2; mt++)
                #pragma unroll
                for (int nt = 0; nt < 8; nt++) {
                    int col = wn * 64 + nt * 8 + 2 * q;
                    float bb0 = b3s[col], bb1 = b3s[col + 1];
                    acc[mt][nt][0] += fmaxf(d[mt][nt][0] + bb0, 0.0f);
                    acc[mt][nt][1] += fmaxf(d[mt][nt][1] + bb1, 0.0f);
                    acc[mt][nt][2] += fmaxf(d[mt][nt][2] + bb0, 0.0f);
                    acc[mt][nt][3] += fmaxf(d[mt][nt][3] + bb1, 0.0f);
                }
        }
    }

    // ---------------- epilogue: out = state + diff ----------------
    #pragma unroll
    for (int mt = 0; mt < 2; mt++)
        #pragma unroll
        for (int nt = 0; nt < 8; nt++) {
            int row = b0 + mrow0 + mt * 16;
            int col = wn * 64 + nt * 8 + 2 * q;
            size_t base = ((size_t)row * S_ + s) * DS_ + col;
            float2 s0 = *(const float2*)(state + base);
            float2 s1 = *(const float2*)(state + base + 8 * (size_t)S_ * DS_);
            float2 o0 = { s0.x + acc[mt][nt][0], s0.y + acc[mt][nt][1] };
            float2 o1 = { s1.x + acc[mt][nt][2], s1.y + acc[mt][nt][3] };
            *(float2*)(out + base)                          = o0;
            *(float2*)(out + base + 8 * (size_t)S_ * DS_)   = o1;
        }
}

extern "C" void kernel_launch(void* const* d_in, const int* in_sizes, int n_in,
                              void* d_out, int out_size)
{
    const float* state = (const float*)d_in[0];
    const float* act   = (const float*)d_in[1];
    const void*  rel   = d_in[2];
    const float* W1 = (const float*)d_in[3];
    const float* b1 = (const float*)d_in[4];
    const float* W2 = (const float*)d_in[5];
    const float* b2 = (const float*)d_in[6];
    const float* W3 = (const float*)d_in[7];
    const float* b3 = (const float*)d_in[8];
    float* out = (float*)d_out;

    const int B = in_sizes[0] / (S_ * DS_);

    cudaFuncSetAttribute(expert_kernel,
                         cudaFuncAttributeMaxDynamicSharedMemorySize, SMEM_BYTES);

    prep_mask_kernel<<<1, 32>>>((const unsigned*)rel);

    dim3 grid(B / TB, S_);
    expert_kernel<<<grid, NTHREADS, SMEM_BYTES>>>(
        state, act, W1, b1, W2, b2, W3, b3, out);
}

// round 3
// speedup vs baseline: 1.7965x; 1.0764x over previous
#include <cuda_runtime.h>
#include <cstdint>

#define S_  16
#define A_  16
#define DA_ 128
#define DS_ 128
#define H_  64
#define TB  128
#define NTHREADS 256

// padded n-strides so B-fragment LDS from [k][n] layout is bank-conflict-free:
// bank = (LDn*q + n)%32 with n = nt*8 + r  ->  need LDn%32 == 8  (8q + r covers 0..31)
#define W1N_LD 72
#define W2N_LD 72
#define W3N_LD 136
#define H_LD   68   // h [row][k]: bank = (68*r + q)%32 = (4r+q)%32 conflict-free

// SMEM word offsets (double-buffered weights, single h buffer)
#define OFF_W1   0                         // 2 x 128*72  = 18432
#define OFF_W2   18432                     // 2 x  64*72  =  9216
#define OFF_W3   27648                     // 2 x  64*136 = 17408
#define OFF_BS   45056                     // 2 x 256 (b1:64, b2:64, b3:128)
#define OFF_H    45568                     // 128*68 = 8704
#define SMEM_WORDS (OFF_H + TB * H_LD)     // 54272
#define SMEM_BYTES (SMEM_WORDS * 4)        // 217088

__device__ int g_cnt[S_];
__device__ int g_list[S_][A_];

__global__ void prep_mask_kernel(const unsigned* __restrict__ rel) {
    if (threadIdx.x != 0) return;
    bool allint = true, allfloat = true;
    for (int i = 0; i < 64; i++) {
        unsigned u = rel[i];
        if (u > 1u) allint = false;
        if (!(u == 0u || u == 0x3F800000u)) allfloat = false;
    }
    int m[S_ * A_];
    if (allint) {
        const int* p = (const int*)rel;
        for (int i = 0; i < S_ * A_; i++) m[i] = (p[i] != 0);
    } else if (allfloat) {
        const float* p = (const float*)rel;
        for (int i = 0; i < S_ * A_; i++) m[i] = (p[i] != 0.0f);
    } else {
        const unsigned char* p = (const unsigned char*)rel;
        for (int i = 0; i < S_ * A_; i++) m[i] = (p[i] != 0);
    }
    for (int s = 0; s < S_; s++) {
        int c = 0;
        for (int a = 0; a < A_; a++)
            if (m[s * A_ + a]) g_list[s][c++] = a;
        g_cnt[s] = c;
    }
}

__device__ __forceinline__ unsigned f2tf(float f) {
    unsigned u;
    asm("cvt.rna.tf32.f32 %0, %1;" : "=r"(u) : "f"(f));
    return u;
}

__device__ __forceinline__ void cpa16(uint32_t dst, const float* src) {
    asm volatile("cp.async.cg.shared.global [%0], [%1], 16;" :: "r"(dst), "l"(src));
}

__device__ __forceinline__ void mma_tf32(float& d0, float& d1, float& d2, float& d3,
                                         unsigned a0, unsigned a1, unsigned a2, unsigned a3,
                                         unsigned b0, unsigned b1) {
    asm volatile(
        "mma.sync.aligned.m16n8k8.row.col.f32.tf32.tf32.f32 "
        "{%0,%1,%2,%3}, {%4,%5,%6,%7}, {%8,%9}, {%0,%1,%2,%3};"
        : "+f"(d0), "+f"(d1), "+f"(d2), "+f"(d3)
        : "r"(a0), "r"(a1), "r"(a2), "r"(a3), "r"(b0), "r"(b1));
}

// stage weights + biases for expert (s,a) into buffer `buf` via cp.async
__device__ __forceinline__ void stage_expert(uint32_t sb, int tid, size_t eo,
                                             const float* W1, const float* b1,
                                             const float* W2, const float* b2,
                                             const float* W3, const float* b3,
                                             int buf)
{
    // W1: 128 rows x 64 floats -> [k][72]
    {
        const float* src = W1 + eo * (DA_ * H_);
        uint32_t db = sb + (OFF_W1 + buf * (DA_ * W1N_LD)) * 4;
        for (int i = tid; i < DA_ * 16; i += NTHREADS) {
            int k = i >> 4, c = (i & 15) * 4;
            cpa16(db + (k * W1N_LD + c) * 4, src + k * H_ + c);
        }
    }
    // W2: 64 rows x 64 floats -> [k][72]
    {
        const float* src = W2 + eo * (H_ * H_);
        uint32_t db = sb + (OFF_W2 + buf * (H_ * W2N_LD)) * 4;
        for (int i = tid; i < H_ * 16; i += NTHREADS) {
            int k = i >> 4, c = (i & 15) * 4;
            cpa16(db + (k * W2N_LD + c) * 4, src + k * H_ + c);
        }
    }
    // W3: 64 rows x 128 floats -> [k][136]
    {
        const float* src = W3 + eo * (H_ * DS_);
        uint32_t db = sb + (OFF_W3 + buf * (H_ * W3N_LD)) * 4;
        for (int i = tid; i < H_ * 32; i += NTHREADS) {
            int k = i >> 5, c = (i & 31) * 4;
            cpa16(db + (k * W3N_LD + c) * 4, src + k * DS_ + c);
        }
    }
    // biases: b1(64) b2(64) b3(128) -> 64 chunks
    if (tid < 64) {
        uint32_t db = sb + (OFF_BS + buf * 256) * 4;
        if (tid < 16)       cpa16(db + tid * 16,               b1 + eo * H_  + tid * 4);
        else if (tid < 32)  cpa16(db + 256 + (tid - 16) * 16,  b2 + eo * H_  + (tid - 16) * 4);
        else                cpa16(db + 512 + (tid - 32) * 16,  b3 + eo * DS_ + (tid - 32) * 4);
    }
}

__global__ __launch_bounds__(NTHREADS, 1)
void expert_kernel(const float* __restrict__ state,
                   const float* __restrict__ act,
                   const float* __restrict__ W1, const float* __restrict__ b1,
                   const float* __restrict__ W2, const float* __restrict__ b2,
                   const float* __restrict__ W3, const float* __restrict__ b3,
                   float* __restrict__ out)
{
    extern __shared__ float sm[];
    const uint32_t sb = (uint32_t)__cvta_generic_to_shared(sm);

    const int s    = blockIdx.y;
    const int b0   = blockIdx.x * TB;
    const int tid  = threadIdx.x;
    const int lane = tid & 31;
    const int warp = tid >> 5;
    const int wm   = warp & 3;
    const int wn   = warp >> 2;
    const int r    = lane >> 2;
    const int q    = lane & 3;

    const int mrow0 = wm * 32 + r;
    const int hcol0 = wn * 32 + 2 * q;

    float acc[2][8][4];
    #pragma unroll
    for (int mt = 0; mt < 2; mt++)
        #pragma unroll
        for (int nt = 0; nt < 8; nt++)
            #pragma unroll
            for (int c = 0; c < 4; c++) acc[mt][nt][c] = 0.0f;

    const int cnt = g_cnt[s];

    if (cnt > 0) {
        stage_expert(sb, tid, (size_t)(s * A_ + g_list[s][0]),
                     W1, b1, W2, b2, W3, b3, 0);
        asm volatile("cp.async.commit_group;" ::: "memory");
    }

    for (int j = 0; j < cnt; j++) {
        const int a   = g_list[s][j];
        const int buf = j & 1;

        asm volatile("cp.async.wait_group 0;" ::: "memory");
        __syncthreads();   // stage j complete; all warps done with buf from iter j-2

        if (j + 1 < cnt) {
            stage_expert(sb, tid, (size_t)(s * A_ + g_list[s][j + 1]),
                         W1, b1, W2, b2, W3, b3, buf ^ 1);
            asm volatile("cp.async.commit_group;" ::: "memory");
        }

        float* W1b = sm + OFF_W1 + buf * (DA_ * W1N_LD);
        float* W2b = sm + OFF_W2 + buf * (H_ * W2N_LD);
        float* W3b = sm + OFF_W3 + buf * (H_ * W3N_LD);
        float* b1s = sm + OFF_BS + buf * 256;
        float* b2s = b1s + 64;
        float* b3s = b1s + 128;
        float* hs  = sm + OFF_H;

        // ------------- GEMM1: h1 = relu(A @ W1 + b1)  M128 N64 K128 -------------
        {
            float d[2][4][4];
            #pragma unroll
            for (int mt = 0; mt < 2; mt++)
                #pragma unroll
                for (int nt = 0; nt < 4; nt++)
                    { d[mt][nt][0]=0; d[mt][nt][1]=0; d[mt][nt][2]=0; d[mt][nt][3]=0; }

            const float* a0p = act + ((size_t)(b0 + mrow0) * A_ + a) * DA_ + q;
            const float* a1p = a0p + (size_t)8  * A_ * DA_;
            const float* a2p = a0p + (size_t)16 * A_ * DA_;
            const float* a3p = a0p + (size_t)24 * A_ * DA_;

            #pragma unroll 4
            for (int kc = 0; kc < 16; kc++) {
                const int k0 = kc * 8;
                unsigned af[2][4], bf[4][2];
                af[0][0] = f2tf(a0p[k0]);     af[0][1] = f2tf(a1p[k0]);
                af[0][2] = f2tf(a0p[k0 + 4]); af[0][3] = f2tf(a1p[k0 + 4]);
                af[1][0] = f2tf(a2p[k0]);     af[1][1] = f2tf(a3p[k0]);
                af[1][2] = f2tf(a2p[k0 + 4]); af[1][3] = f2tf(a3p[k0 + 4]);
                #pragma unroll
                for (int nt = 0; nt < 4; nt++) {
                    int n = wn * 32 + nt * 8 + r;
                    bf[nt][0] = f2tf(W1b[(k0 + q) * W1N_LD + n]);
                    bf[nt][1] = f2tf(W1b[(k0 + q + 4) * W1N_LD + n]);
                }
                #pragma unroll
                for (int mt = 0; mt < 2; mt++)
                    #pragma unroll
                    for (int nt = 0; nt < 4; nt++)
                        mma_tf32(d[mt][nt][0], d[mt][nt][1], d[mt][nt][2], d[mt][nt][3],
                                 af[mt][0], af[mt][1], af[mt][2], af[mt][3],
                                 bf[nt][0], bf[nt][1]);
            }
            #pragma unroll
            for (int mt = 0; mt < 2; mt++)
                #pragma unroll
                for (int nt = 0; nt < 4; nt++) {
                    int col = hcol0 + nt * 8;
                    float bb0 = b1s[col], bb1 = b1s[col + 1];
                    int row = mrow0 + mt * 16;
                    float2 v0 = { fmaxf(d[mt][nt][0] + bb0, 0.0f), fmaxf(d[mt][nt][1] + bb1, 0.0f) };
                    float2 v1 = { fmaxf(d[mt][nt][2] + bb0, 0.0f), fmaxf(d[mt][nt][3] + bb1, 0.0f) };
                    *(float2*)(hs + row * H_LD + col)       = v0;
                    *(float2*)(hs + (row + 8) * H_LD + col) = v1;
                }
        }
        __syncthreads();

        // ------------- GEMM2: h2 = relu(h1 @ W2 + b2)  M128 N64 K64 -------------
        {
            // preload ALL A fragments (so h buffer can be overwritten in place)
            unsigned a2r[8][2][4];
            #pragma unroll
            for (int kc = 0; kc < 8; kc++) {
                const int k0 = kc * 8;
                #pragma unroll
                for (int mt = 0; mt < 2; mt++) {
                    const float* hb = hs + (mrow0 + mt * 16) * H_LD + k0 + q;
                    a2r[kc][mt][0] = f2tf(hb[0]);
                    a2r[kc][mt][1] = f2tf(hb[8 * H_LD]);
                    a2r[kc][mt][2] = f2tf(hb[4]);
                    a2r[kc][mt][3] = f2tf(hb[8 * H_LD + 4]);
                }
            }
            __syncthreads();   // all warps have read h1; safe to overwrite

            float d[2][4][4];
            #pragma unroll
            for (int mt = 0; mt < 2; mt++)
                #pragma unroll
                for (int nt = 0; nt < 4; nt++)
                    { d[mt][nt][0]=0; d[mt][nt][1]=0; d[mt][nt][2]=0; d[mt][nt][3]=0; }
            #pragma unroll
            for (int kc = 0; kc < 8; kc++) {
                const int k0 = kc * 8;
                unsigned bf[4][2];
                #pragma unroll
                for (int nt = 0; nt < 4; nt++) {
                    int n = wn * 32 + nt * 8 + r;
                    bf[nt][0] = f2tf(W2b[(k0 + q) * W2N_LD + n]);
                    bf[nt][1] = f2tf(W2b[(k0 + q + 4) * W2N_LD + n]);
                }
                #pragma unroll
                for (int mt = 0; mt < 2; mt++)
                    #pragma unroll
                    for (int nt = 0; nt < 4; nt++)
                        mma_tf32(d[mt][nt][0], d[mt][nt][1], d[mt][nt][2], d[mt][nt][3],
                                 a2r[kc][mt][0], a2r[kc][mt][1], a2r[kc][mt][2], a2r[kc][mt][3],
                                 bf[nt][0], bf[nt][1]);
            }
            #pragma unroll
            for (int mt = 0; mt < 2; mt++)
                #pragma unroll
                for (int nt = 0; nt < 4; nt++) {
                    int col = hcol0 + nt * 8;
                    float bb0 = b2s[col], bb1 = b2s[col + 1];
                    int row = mrow0 + mt * 16;
                    float2 v0 = { fmaxf(d[mt][nt][0] + bb0, 0.0f), fmaxf(d[mt][nt][1] + bb1, 0.0f) };
                    float2 v1 = { fmaxf(d[mt][nt][2] + bb0, 0.0f), fmaxf(d[mt][nt][3] + bb1, 0.0f) };
                    *(float2*)(hs + row * H_LD + col)       = v0;
                    *(float2*)(hs + (row + 8) * H_LD + col) = v1;
                }
        }
        __syncthreads();

        // ------------- GEMM3: acc += relu(h2 @ W3 + b3)  M128 N128 K64 -------------
        {
            float d[2][8][4];
            #pragma unroll
            for (int mt = 0; mt < 2; mt++)
                #pragma unroll
                for (int nt = 0; nt < 8; nt++)
                    { d[mt][nt][0]=0; d[mt][nt][1]=0; d[mt][nt][2]=0; d[mt][nt][3]=0; }
            #pragma unroll 2
            for (int kc = 0; kc < 8; kc++) {
                const int k0 = kc * 8;
                unsigned af[2][4], bf[8][2];
                #pragma unroll
                for (int mt = 0; mt < 2; mt++) {
                    const float* hb = hs + (mrow0 + mt * 16) * H_LD + k0 + q;
                    af[mt][0] = f2tf(hb[0]);
                    af[mt][1] = f2tf(hb[8 * H_LD]);
                    af[mt][2] = f2tf(hb[4]);
                    af[mt][3] = f2tf(hb[8 * H_LD + 4]);
                }
                #pragma unroll
                for (int nt = 0; nt < 8; nt++) {
                    int n = wn * 64 + nt * 8 + r;
                    bf[nt][0] = f2tf(W3b[(k0 + q) * W3N_LD + n]);
                    bf[nt][1] = f2tf(W3b[(k0 + q + 4) * W3N_LD + n]);
                }
                #pragma unroll
                for (int mt = 0; mt < 2; mt++)
                    #pragma unroll
                    for (int nt = 0; nt < 8; nt++)
                        mma_tf32(d[mt][nt][0], d[mt][nt][1], d[mt][nt][2], d[mt][nt][3],
                                 af[mt][0], af[mt][1], af[mt][2], af[mt][3],
                                 bf[nt][0], bf[nt][1]);
            }
            #pragma unroll
            for (int mt = 0; mt < 2; mt++)
                #pragma unroll
                for (int nt = 0; nt < 8; nt++) {
                    int col = wn * 64 + nt * 8 + 2 * q;
                    float bb0 = b3s[col], bb1 = b3s[col + 1];
                    acc[mt][nt][0] += fmaxf(d[mt][nt][0] + bb0, 0.0f);
                    acc[mt][nt][1] += fmaxf(d[mt][nt][1] + bb1, 0.0f);
                    acc[mt][nt][2] += fmaxf(d[mt][nt][2] + bb0, 0.0f);
                    acc[mt][nt][3] += fmaxf(d[mt][nt][3] + bb1, 0.0f);
                }
        }
    }

    // ------------- epilogue: out = state + diff -------------
    #pragma unroll
    for (int mt = 0; mt < 2; mt++)
        #pragma unroll
        for (int nt = 0; nt < 8; nt++) {
            int row = b0 + mrow0 + mt * 16;
            int col = wn * 64 + nt * 8 + 2 * q;
            size_t base = ((size_t)row * S_ + s) * DS_ + col;
            float2 s0 = *(const float2*)(state + base);
            float2 s1 = *(const float2*)(state + base + 8 * (size_t)S_ * DS_);
            float2 o0 = { s0.x + acc[mt][nt][0], s0.y + acc[mt][nt][1] };
            float2 o1 = { s1.x + acc[mt][nt][2], s1.y + acc[mt][nt][3] };
            *(float2*)(out + base)                        = o0;
            *(float2*)(out + base + 8 * (size_t)S_ * DS_) = o1;
        }
}

extern "C" void kernel_launch(void* const* d_in, const int* in_sizes, int n_in,
                              void* d_out, int out_size)
{
    const float* state = (const float*)d_in[0];
    const float* act   = (const float*)d_in[1];
    const void*  rel   = d_in[2];
    const float* W1 = (const float*)d_in[3];
    const float* b1 = (const float*)d_in[4];
    const float* W2 = (const float*)d_in[5];
    const float* b2 = (const float*)d_in[6];
    const float* W3 = (const float*)d_in[7];
    const float* b3 = (const float*)d_in[8];
    float* out = (float*)d_out;

    const int B = in_sizes[0] / (S_ * DS_);

    cudaFuncSetAttribute(expert_kernel,
                         cudaFuncAttributeMaxDynamicSharedMemorySize, SMEM_BYTES);

    prep_mask_kernel<<<1, 32>>>((const unsigned*)rel);

    dim3 grid(B / TB, S_);
    expert_kernel<<<grid, NTHREADS, SMEM_BYTES>>>(
        state, act, W1, b1, W2, b2, W3, b3, out);
}

// round 7
// speedup vs baseline: 1.8991x; 1.0571x over previous
#include <cuda_runtime.h>
#include <cstdint>

#define S_  16
#define A_  16
#define DA_ 128
#define DS_ 128
#define H_  64
#define TB  64
#define NTHREADS 128

#define H_LD 68

// SMEM byte offsets
#define SM_W1 0                          // [k=128][64] xor-swizzled = 32768
#define SM_W2 32768                      // [k=64][64]               = 16384
#define SM_W3 49152                      // [k=64][128]              = 32768
#define SM_H  81920                      // [64][68]                 = 17408
#define SM_B1 99328                      // 64 f32
#define SM_B2 99584                      // 64 f32
#define SM_B3 99840                      // 128 f32
#define SMEM_BYTES 100352

__device__ int g_cnt[S_];
__device__ int g_list[S_][A_];

__global__ void prep_mask_kernel(const unsigned* __restrict__ rel) {
    if (threadIdx.x != 0) return;
    bool allint = true, allfloat = true;
    for (int i = 0; i < 64; i++) {
        unsigned u = rel[i];
        if (u > 1u) allint = false;
        if (!(u == 0u || u == 0x3F800000u)) allfloat = false;
    }
    int m[S_ * A_];
    if (allint) {
        const int* p = (const int*)rel;
        for (int i = 0; i < S_ * A_; i++) m[i] = (p[i] != 0);
    } else if (allfloat) {
        const float* p = (const float*)rel;
        for (int i = 0; i < S_ * A_; i++) m[i] = (p[i] != 0.0f);
    } else {
        const unsigned char* p = (const unsigned char*)rel;
        for (int i = 0; i < S_ * A_; i++) m[i] = (p[i] != 0);
    }
    for (int s = 0; s < S_; s++) {
        int c = 0;
        for (int a = 0; a < A_; a++)
            if (m[s * A_ + a]) g_list[s][c++] = a;
        g_cnt[s] = c;
    }
}

__device__ __forceinline__ unsigned f2tf(float f) {
    unsigned u;
    asm("cvt.rna.tf32.f32 %0, %1;" : "=r"(u) : "f"(f));
    return u;
}
__device__ __forceinline__ unsigned u2tf(unsigned x) {   // rna on raw fp32 bits
    unsigned u;
    asm("cvt.rna.tf32.f32 %0, %1;" : "=r"(u) : "r"(x));
    return u;
}

__device__ __forceinline__ void cpa16(uint32_t dst, const void* src) {
    asm volatile("cp.async.cg.shared.global [%0], [%1], 16;" :: "r"(dst), "l"(src));
}
#define CP_COMMIT() asm volatile("cp.async.commit_group;" ::: "memory")
#define CP_WAIT2()  asm volatile("cp.async.wait_group 2;" ::: "memory")

__device__ __forceinline__ void mma_tf32(float& d0, float& d1, float& d2, float& d3,
                                         unsigned a0, unsigned a1, unsigned a2, unsigned a3,
                                         unsigned b0, unsigned b1) {
    asm volatile(
        "mma.sync.aligned.m16n8k8.row.col.f32.tf32.tf32.f32 "
        "{%0,%1,%2,%3}, {%4,%5,%6,%7}, {%8,%9}, {%0,%1,%2,%3};"
        : "+f"(d0), "+f"(d1), "+f"(d2), "+f"(d3)
        : "r"(a0), "r"(a1), "r"(a2), "r"(a3), "r"(b0), "r"(b1));
}

// --- staging helpers (one cp.async group each; ALL threads must call) ---
__device__ __forceinline__ void stage1(uint32_t sb, int tid, size_t eo,
                                       const float* W1, const float* b1) {
    const float* src = W1 + eo * (DA_ * H_);
    #pragma unroll
    for (int it = 0; it < 16; it++) {
        int i = tid + it * NTHREADS;            // 0..2047
        int k = i >> 4, c = (i & 15) * 4;
        cpa16(sb + SM_W1 + (k * 64 + (c ^ (8 * (k & 3)))) * 4, src + k * H_ + c);
    }
    if (tid < 16) cpa16(sb + SM_B1 + tid * 16, b1 + eo * H_ + tid * 4);
}
__device__ __forceinline__ void stage2(uint32_t sb, int tid, size_t eo,
                                       const float* W2, const float* b2) {
    const float* src = W2 + eo * (H_ * H_);
    #pragma unroll
    for (int it = 0; it < 8; it++) {
        int i = tid + it * NTHREADS;            // 0..1023
        int k = i >> 4, c = (i & 15) * 4;
        cpa16(sb + SM_W2 + (k * 64 + (c ^ (8 * (k & 3)))) * 4, src + k * H_ + c);
    }
    if (tid < 16) cpa16(sb + SM_B2 + tid * 16, b2 + eo * H_ + tid * 4);
}
__device__ __forceinline__ void stage3(uint32_t sb, int tid, size_t eo,
                                       const float* W3, const float* b3) {
    const float* src = W3 + eo * (H_ * DS_);
    #pragma unroll
    for (int it = 0; it < 16; it++) {
        int i = tid + it * NTHREADS;            // 0..2047
        int k = i >> 5, c = (i & 31) * 4;
        cpa16(sb + SM_W3 + (k * 128 + (c ^ (8 * (k & 3)))) * 4, src + k * DS_ + c);
    }
    if (tid < 32) cpa16(sb + SM_B3 + tid * 16, b3 + eo * DS_ + tid * 4);
}

__global__ __launch_bounds__(NTHREADS, 2)
void expert_kernel(const float* __restrict__ state,
                   const float* __restrict__ act,
                   const float* __restrict__ W1, const float* __restrict__ b1,
                   const float* __restrict__ W2, const float* __restrict__ b2,
                   const float* __restrict__ W3, const float* __restrict__ b3,
                   float* __restrict__ out)
{
    extern __shared__ char smem[];
    const uint32_t sb = (uint32_t)__cvta_generic_to_shared(smem);
    const unsigned* W1u = (const unsigned*)(smem + SM_W1);
    const unsigned* W2u = (const unsigned*)(smem + SM_W2);
    const unsigned* W3u = (const unsigned*)(smem + SM_W3);
    float*    hs  = (float*)(smem + SM_H);
    const unsigned* hu = (const unsigned*)(smem + SM_H);
    const float* b1s = (const float*)(smem + SM_B1);
    const float* b2s = (const float*)(smem + SM_B2);
    const float* b3s = (const float*)(smem + SM_B3);

    const int s    = blockIdx.y;
    const int b0   = blockIdx.x * TB;
    const int tid  = threadIdx.x;
    const int lane = tid & 31;
    const int warp = tid >> 5;
    const int wm   = warp & 1;      // 2 warp-rows (m32)
    const int wn   = warp >> 1;     // 2 warp-cols
    const int r    = lane >> 2;
    const int q    = lane & 3;
    const int xq   = 8 * q;         // column XOR for B-frag reads

    const int mrow0 = wm * 32 + r;

    float acc[2][8][4];
    #pragma unroll
    for (int mt = 0; mt < 2; mt++)
        #pragma unroll
        for (int nt = 0; nt < 8; nt++)
            #pragma unroll
            for (int c = 0; c < 4; c++) acc[mt][nt][c] = 0.0f;

    const int cnt = g_cnt[s];

    if (cnt > 0) {
        size_t eo = (size_t)(s * A_ + g_list[s][0]);
        stage1(sb, tid, eo, W1, b1); CP_COMMIT();
        stage2(sb, tid, eo, W2, b2); CP_COMMIT();
        stage3(sb, tid, eo, W3, b3); CP_COMMIT();
    }

    for (int j = 0; j < cnt; j++) {
        const int a = g_list[s][j];
        const size_t eon = (j + 1 < cnt) ? (size_t)(s * A_ + g_list[s][j + 1]) : 0;

        CP_WAIT2();          // W1(j), b1(j) landed
        __syncthreads();     // publish W1; everyone done with h/W3 from prev iter

        // ---- GEMM1: h1 = relu(A @ W1 + b1), M64 N64 K128 ----
        {
            float d[2][4][4];
            #pragma unroll
            for (int mt = 0; mt < 2; mt++)
                #pragma unroll
                for (int nt = 0; nt < 4; nt++)
                    { d[mt][nt][0]=0; d[mt][nt][1]=0; d[mt][nt][2]=0; d[mt][nt][3]=0; }

            const float* a0p = act + ((size_t)(b0 + mrow0) * A_ + a) * DA_ + q;
            const float* a1p = a0p + (size_t)8  * A_ * DA_;
            const float* a2p = a0p + (size_t)16 * A_ * DA_;
            const float* a3p = a0p + (size_t)24 * A_ * DA_;

            #pragma unroll 4
            for (int kc = 0; kc < 16; kc++) {
                const int k0 = kc * 8;
                unsigned af[2][4], bf[4][2];
                af[0][0] = f2tf(a0p[k0]);     af[0][1] = f2tf(a1p[k0]);
                af[0][2] = f2tf(a0p[k0 + 4]); af[0][3] = f2tf(a1p[k0 + 4]);
                af[1][0] = f2tf(a2p[k0]);     af[1][1] = f2tf(a3p[k0]);
                af[1][2] = f2tf(a2p[k0 + 4]); af[1][3] = f2tf(a3p[k0 + 4]);
                #pragma unroll
                for (int nt = 0; nt < 4; nt++) {
                    int n = (wn * 32 + nt * 8 + r) ^ xq;
                    bf[nt][0] = u2tf(W1u[(k0 + q) * 64 + n]);
                    bf[nt][1] = u2tf(W1u[(k0 + q + 4) * 64 + n]);
                }
                #pragma unroll
                for (int mt = 0; mt < 2; mt++)
                    #pragma unroll
                    for (int nt = 0; nt < 4; nt++)
                        mma_tf32(d[mt][nt][0], d[mt][nt][1], d[mt][nt][2], d[mt][nt][3],
                                 af[mt][0], af[mt][1], af[mt][2], af[mt][3],
                                 bf[nt][0], bf[nt][1]);
            }
            #pragma unroll
            for (int mt = 0; mt < 2; mt++)
                #pragma unroll
                for (int nt = 0; nt < 4; nt++) {
                    int col = wn * 32 + nt * 8 + 2 * q;
                    float bb0 = b1s[col], bb1 = b1s[col + 1];
                    int row = mrow0 + mt * 16;
                    uint2 v0 = { f2tf(fmaxf(d[mt][nt][0] + bb0, 0.0f)),
                                 f2tf(fmaxf(d[mt][nt][1] + bb1, 0.0f)) };
                    uint2 v1 = { f2tf(fmaxf(d[mt][nt][2] + bb0, 0.0f)),
                                 f2tf(fmaxf(d[mt][nt][3] + bb1, 0.0f)) };
                    *(uint2*)(hs + row * H_LD + col)       = v0;
                    *(uint2*)(hs + (row + 8) * H_LD + col) = v1;
                }
        }
        __syncthreads();     // ALL warps done reading W1(j)/b1(j) before overwrite
        if (j + 1 < cnt) { stage1(sb, tid, eon, W1, b1); }
        CP_COMMIT();
        CP_WAIT2();          // W2(j), b2(j) landed
        __syncthreads();     // publish W2; h1 visible to all warps

        // ---- GEMM2: h2 = relu(h1 @ W2 + b2), M64 N64 K64 (in-place h) ----
        {
            unsigned a2r[8][2][4];
            #pragma unroll
            for (int kc = 0; kc < 8; kc++) {
                const int k0 = kc * 8;
                #pragma unroll
                for (int mt = 0; mt < 2; mt++) {
                    const unsigned* hb = hu + (mrow0 + mt * 16) * H_LD + k0 + q;
                    a2r[kc][mt][0] = hb[0];
                    a2r[kc][mt][1] = hb[8 * H_LD];
                    a2r[kc][mt][2] = hb[4];
                    a2r[kc][mt][3] = hb[8 * H_LD + 4];
                }
            }
            __syncthreads();   // all reads of h1 done; safe to overwrite

            float d[2][4][4];
            #pragma unroll
            for (int mt = 0; mt < 2; mt++)
                #pragma unroll
                for (int nt = 0; nt < 4; nt++)
                    { d[mt][nt][0]=0; d[mt][nt][1]=0; d[mt][nt][2]=0; d[mt][nt][3]=0; }
            #pragma unroll
            for (int kc = 0; kc < 8; kc++) {
                const int k0 = kc * 8;
                unsigned bf[4][2];
                #pragma unroll
                for (int nt = 0; nt < 4; nt++) {
                    int n = (wn * 32 + nt * 8 + r) ^ xq;
                    bf[nt][0] = u2tf(W2u[(k0 + q) * 64 + n]);
                    bf[nt][1] = u2tf(W2u[(k0 + q + 4) * 64 + n]);
                }
                #pragma unroll
                for (int mt = 0; mt < 2; mt++)
                    #pragma unroll
                    for (int nt = 0; nt < 4; nt++)
                        mma_tf32(d[mt][nt][0], d[mt][nt][1], d[mt][nt][2], d[mt][nt][3],
                                 a2r[kc][mt][0], a2r[kc][mt][1], a2r[kc][mt][2], a2r[kc][mt][3],
                                 bf[nt][0], bf[nt][1]);
            }
            #pragma unroll
            for (int mt = 0; mt < 2; mt++)
                #pragma unroll
                for (int nt = 0; nt < 4; nt++) {
                    int col = wn * 32 + nt * 8 + 2 * q;
                    float bb0 = b2s[col], bb1 = b2s[col + 1];
                    int row = mrow0 + mt * 16;
                    uint2 v0 = { f2tf(fmaxf(d[mt][nt][0] + bb0, 0.0f)),
                                 f2tf(fmaxf(d[mt][nt][1] + bb1, 0.0f)) };
                    uint2 v1 = { f2tf(fmaxf(d[mt][nt][2] + bb0, 0.0f)),
                                 f2tf(fmaxf(d[mt][nt][3] + bb1, 0.0f)) };
                    *(uint2*)(hs + row * H_LD + col)       = v0;
                    *(uint2*)(hs + (row + 8) * H_LD + col) = v1;
                }
        }
        __syncthreads();     // ALL warps done reading W2(j)/b2(j) before overwrite
        if (j + 1 < cnt) { stage2(sb, tid, eon, W2, b2); }
        CP_COMMIT();
        CP_WAIT2();          // W3(j), b3(j) landed
        __syncthreads();     // publish W3; h2 visible to all warps

        // ---- GEMM3: acc += relu(h2 @ W3 + b3), M64 N128 K64 ----
        {
            float d[2][8][4];
            #pragma unroll
            for (int mt = 0; mt < 2; mt++)
                #pragma unroll
                for (int nt = 0; nt < 8; nt++)
                    { d[mt][nt][0]=0; d[mt][nt][1]=0; d[mt][nt][2]=0; d[mt][nt][3]=0; }
            #pragma unroll 2
            for (int kc = 0; kc < 8; kc++) {
                const int k0 = kc * 8;
                unsigned af[2][4], bf[8][2];
                #pragma unroll
                for (int mt = 0; mt < 2; mt++) {
                    const unsigned* hb = hu + (mrow0 + mt * 16) * H_LD + k0 + q;
                    af[mt][0] = hb[0];
                    af[mt][1] = hb[8 * H_LD];
                    af[mt][2] = hb[4];
                    af[mt][3] = hb[8 * H_LD + 4];
                }
                #pragma unroll
                for (int nt = 0; nt < 8; nt++) {
                    int n = (wn * 64 + nt * 8 + r) ^ xq;
                    bf[nt][0] = u2tf(W3u[(k0 + q) * 128 + n]);
                    bf[nt][1] = u2tf(W3u[(k0 + q + 4) * 128 + n]);
                }
                #pragma unroll
                for (int mt = 0; mt < 2; mt++)
                    #pragma unroll
                    for (int nt = 0; nt < 8; nt++)
                        mma_tf32(d[mt][nt][0], d[mt][nt][1], d[mt][nt][2], d[mt][nt][3],
                                 af[mt][0], af[mt][1], af[mt][2], af[mt][3],
                                 bf[nt][0], bf[nt][1]);
            }
            #pragma unroll
            for (int mt = 0; mt < 2; mt++)
                #pragma unroll
                for (int nt = 0; nt < 8; nt++) {
                    int col = wn * 64 + nt * 8 + 2 * q;
                    float bb0 = b3s[col], bb1 = b3s[col + 1];
                    acc[mt][nt][0] += fmaxf(d[mt][nt][0] + bb0, 0.0f);
                    acc[mt][nt][1] += fmaxf(d[mt][nt][1] + bb1, 0.0f);
                    acc[mt][nt][2] += fmaxf(d[mt][nt][2] + bb0, 0.0f);
                    acc[mt][nt][3] += fmaxf(d[mt][nt][3] + bb1, 0.0f);
                }
        }
        __syncthreads();     // ALL warps done reading W3(j)/b3(j)/h2 before overwrite
        if (j + 1 < cnt) { stage3(sb, tid, eon, W3, b3); }
        CP_COMMIT();
    }

    // ---- epilogue: out = state + diff ----
    #pragma unroll
    for (int mt = 0; mt < 2; mt++)
        #pragma unroll
        for (int nt = 0; nt < 8; nt++) {
            int row = b0 + mrow0 + mt * 16;
            int col = wn * 64 + nt * 8 + 2 * q;
            size_t base = ((size_t)row * S_ + s) * DS_ + col;
            float2 s0 = *(const float2*)(state + base);
            float2 s1 = *(const float2*)(state + base + 8 * (size_t)S_ * DS_);
            float2 o0 = { s0.x + acc[mt][nt][0], s0.y + acc[mt][nt][1] };
            float2 o1 = { s1.x + acc[mt][nt][2], s1.y + acc[mt][nt][3] };
            *(float2*)(out + base)                        = o0;
            *(float2*)(out + base + 8 * (size_t)S_ * DS_) = o1;
        }
}

extern "C" void kernel_launch(void* const* d_in, const int* in_sizes, int n_in,
                              void* d_out, int out_size)
{
    const float* state = (const float*)d_in[0];
    const float* act   = (const float*)d_in[1];
    const void*  rel   = d_in[2];
    const float* W1 = (const float*)d_in[3];
    const float* b1 = (const float*)d_in[4];
    const float* W2 = (const float*)d_in[5];
    const float* b2 = (const float*)d_in[6];
    const float* W3 = (const float*)d_in[7];
    const float* b3 = (const float*)d_in[8];
    float* out = (float*)d_out;

    const int B = in_sizes[0] / (S_ * DS_);

    cudaFuncSetAttribute(expert_kernel,
                         cudaFuncAttributeMaxDynamicSharedMemorySize, SMEM_BYTES);

    prep_mask_kernel<<<1, 32>>>((const unsigned*)rel);

    dim3 grid(B / TB, S_);
    expert_kernel<<<grid, NTHREADS, SMEM_BYTES>>>(
        state, act, W1, b1, W2, b2, W3, b3, out);
}